// round 11
// baseline (speedup 1.0000x reference)
#include <cuda_runtime.h>
#include <cuda_bf16.h>
#include <cstdint>
#include <cstddef>
#include <math.h>

#define B_TOT 131072
#define D_IN 128
#define HID 256
#define VTOT 6
#define TSTEPS 6
typedef unsigned long long ull;

extern "C" __device__ float __nv_logf(float);
extern "C" __device__ float __nv_expf(float);

__device__ __align__(16) float g_h[(size_t)B_TOT * HID];
__device__ __align__(16) float g_z[(size_t)B_TOT * HID];
__device__ __align__(16) float g_rh[(size_t)B_TOT * HID];
__device__ unsigned char g_state[B_TOT];
__device__ __align__(16) float g_E[3][8][HID];
__device__ uint32_t g_keyw[12];
__device__ int g_perm[2][B_TOT];
__device__ int g_cnt[TSTEPS + 2];
__device__ __align__(16) __nv_bfloat16 g_Wb[3][3][HID][HID];  // [gate][split][n][k]

__device__ __forceinline__ void threefry2x32(uint32_t k0, uint32_t k1,
                                             uint32_t c0, uint32_t c1,
                                             uint32_t& o0, uint32_t& o1) {
  uint32_t ks2 = k0 ^ k1 ^ 0x1BD11BDAu;
  uint32_t x0 = c0 + k0, x1 = c1 + k1;
#define TF_R(r) { x0 += x1; x1 = (x1 << (r)) | (x1 >> (32 - (r))); x1 ^= x0; }
  TF_R(13) TF_R(15) TF_R(26) TF_R(6)
  x0 += k1;  x1 += ks2 + 1u;
  TF_R(17) TF_R(29) TF_R(16) TF_R(24)
  x0 += ks2; x1 += k0 + 2u;
  TF_R(13) TF_R(15) TF_R(26) TF_R(6)
  x0 += k0;  x1 += k1 + 3u;
  TF_R(17) TF_R(29) TF_R(16) TF_R(24)
  x0 += k1;  x1 += ks2 + 4u;
  TF_R(13) TF_R(15) TF_R(26) TF_R(6)
  x0 += ks2; x1 += k0 + 5u;
#undef TF_R
  o0 = x0; o1 = x1;
}

__device__ __forceinline__ void fma2(ull& d, ull a, ull b) {
  asm("fma.rn.f32x2 %0, %1, %2, %0;" : "+l"(d) : "l"(a), "l"(b));
}
__device__ __forceinline__ ull pack2(float a) {
  ull r; asm("mov.b64 %0, {%1, %1};" : "=l"(r) : "f"(a)); return r;
}
__device__ __forceinline__ float2 unpack2(ull v) {
  float2 r; asm("mov.b64 {%0, %1}, %2;" : "=f"(r.x), "=f"(r.y) : "l"(v)); return r;
}
__device__ __forceinline__ void cp16(void* dst, const void* src) {
  unsigned d = (unsigned)__cvta_generic_to_shared(dst);
  asm volatile("cp.async.cg.shared.global [%0], [%1], 16;" :: "r"(d), "l"(src));
}
__device__ __forceinline__ uint32_t smem_u32(const void* p) {
  uint32_t a;
  asm("{ .reg .u64 t; cvta.to.shared.u64 t, %1; cvt.u32.u64 %0, t; }" : "=r"(a) : "l"(p));
  return a;
}
__device__ __forceinline__ float xla_tanh(float x) {
  float ax = fabsf(x);
  if (ax < 0.0004f) return x;
  float xc = fminf(fmaxf(x, -9.0f), 9.0f);
  float x2 = __fmul_rn(xc, xc);
  float num = -2.76076847742355e-16f;
  num = __fadd_rn(__fmul_rn(x2, num), 2.00018790482477e-13f);
  num = __fadd_rn(__fmul_rn(x2, num), -8.60467152213735e-11f);
  num = __fadd_rn(__fmul_rn(x2, num), 5.12229709037114e-08f);
  num = __fadd_rn(__fmul_rn(x2, num), 1.48572235717979e-05f);
  num = __fadd_rn(__fmul_rn(x2, num), 6.37261928875436e-04f);
  num = __fadd_rn(__fmul_rn(x2, num), 4.89352455891786e-03f);
  num = __fmul_rn(xc, num);
  float den = 1.19825839466702e-06f;
  den = __fadd_rn(__fmul_rn(x2, den), 1.18534705686654e-04f);
  den = __fadd_rn(__fmul_rn(x2, den), 2.26843463243900e-03f);
  den = __fadd_rn(__fmul_rn(x2, den), 4.89352518554385e-03f);
  return __fdiv_rn(num, den);
}
__device__ __forceinline__ float sigmoid_(float x) {
  return __fadd_rn(0.5f, __fmul_rn(0.5f, xla_tanh(__fmul_rn(0.5f, x))));
}
__device__ __forceinline__ void split3(float x, __nv_bfloat16& b1,
                                       __nv_bfloat16& b2, __nv_bfloat16& b3) {
  b1 = __float2bfloat16(x);
  float r1 = __fadd_rn(x, -__bfloat162float(b1));
  b2 = __float2bfloat16(r1);
  float r2 = __fadd_rn(r1, -__bfloat162float(b2));
  b3 = __float2bfloat16(r2);
}
__device__ __forceinline__ uint32_t bfpack(__nv_bfloat16 a, __nv_bfloat16 b) {
  __nv_bfloat162 v(a, b);
  return reinterpret_cast<uint32_t&>(v);
}

// ---- init ----
__global__ void init_kernel(float* __restrict__ out) {
  const int gid = blockIdx.x * blockDim.x + threadIdx.x;
  const int nthr = gridDim.x * blockDim.x;
  for (size_t j = gid; j < (size_t)B_TOT * 36; j += nthr) out[j] = 0.f;
  if (gid < B_TOT) {
    out[(size_t)B_TOT * 36 + gid] = 0.f;
    out[(size_t)B_TOT * 37 + gid] = 0.f;
    g_state[gid] = 7;
    g_perm[0][gid] = gid;
  }
  if (gid < TSTEPS + 2) g_cnt[gid] = (gid == 0) ? B_TOT : 0;
  if (gid < 6) {
    uint32_t a, b;
    threefry2x32(0u, 42u, 0u, (uint32_t)gid, a, b);
    g_keyw[2 * gid] = a; g_keyw[2 * gid + 1] = b;
  }
}

__global__ void precompute_E(const float* __restrict__ W_embed,
                             const float* __restrict__ b_embed,
                             const float* __restrict__ Wz, const float* __restrict__ bz,
                             const float* __restrict__ Wr, const float* __restrict__ br,
                             const float* __restrict__ Wh, const float* __restrict__ bh,
                             const float* __restrict__ start_embed) {
  int s = blockIdx.x, m = blockIdx.y, j = threadIdx.x;
  const float* W  = (m == 0) ? Wz : (m == 1) ? Wr : Wh;
  const float* bb = (m == 0) ? bz : (m == 1) ? br : bh;
  float acc = bb[j];
  for (int k = 0; k < HID; k++) {
    float e;
    if (s == 7) e = start_embed[k];
    else { e = b_embed[k]; if (s < 6) e += W_embed[s * HID + k]; }
    acc = fmaf(e, W[k * HID + j], acc);
  }
  g_E[m][s][j] = acc;
}

__global__ void split_W(const float* __restrict__ Wz, const float* __restrict__ Wr,
                        const float* __restrict__ Wh) {
  const int n = blockIdx.x, m = blockIdx.y, k = threadIdx.x;
  const float* W = (m == 0) ? Wz : (m == 1) ? Wr : Wh;  // bottom 256 rows, [k][n]
  __nv_bfloat16 b1, b2, b3;
  split3(W[(size_t)k * HID + n], b1, b2, b3);
  g_Wb[m][0][n][k] = b1; g_Wb[m][1][n][k] = b2; g_Wb[m][2][n][k] = b3;
}

// ---- encoder: R8 FFMA2 core, g_h only ----
__global__ void __launch_bounds__(256, 2) enc_k(
    const float* __restrict__ A, const float* __restrict__ Bw,
    const float* __restrict__ bias) {
  constexpr int BM = 64, BN = 256, BK = 16, APAD = BM + 4;
  __shared__ __align__(16) float As[2][BK][APAD];
  __shared__ __align__(16) float Bs[2][BK][BN];
  const int rowBase = blockIdx.x * BM;
  const int tid = threadIdx.x, tc = tid & 31, tr = tid >> 5;
  const int a_row = tid >> 2, a_seg = (tid & 3) << 2;
  const float* Ag = A + (size_t)(rowBase + a_row) * D_IN + a_seg;
  ull acc[8][4];
#pragma unroll
  for (int r = 0; r < 8; r++)
#pragma unroll
    for (int p = 0; p < 4; p++) acc[r][p] = 0ull;
  const int NC = D_IN / BK;
  float4 rA = *reinterpret_cast<const float4*>(Ag);
#pragma unroll
  for (int i = 0; i < 4; i++) {
    int idx = tid + i * 256, kr = idx >> 6, cs = (idx & 63) << 2;
    cp16(&Bs[0][kr][cs], Bw + (size_t)kr * BN + cs);
  }
  asm volatile("cp.async.commit_group;");
  As[0][a_seg][a_row] = rA.x; As[0][a_seg + 1][a_row] = rA.y;
  As[0][a_seg + 2][a_row] = rA.z; As[0][a_seg + 3][a_row] = rA.w;
  rA = *reinterpret_cast<const float4*>(Ag + BK);
  for (int c = 0; c < NC; c++) {
    asm volatile("cp.async.wait_group 0;");
    __syncthreads();
    if (c + 1 < NC) {
      const int nb = (c + 1) & 1;
#pragma unroll
      for (int i = 0; i < 4; i++) {
        int idx = tid + i * 256, kr = idx >> 6, cs = (idx & 63) << 2;
        cp16(&Bs[nb][kr][cs], Bw + (size_t)((c + 1) * BK + kr) * BN + cs);
      }
      asm volatile("cp.async.commit_group;");
      As[nb][a_seg][a_row] = rA.x; As[nb][a_seg + 1][a_row] = rA.y;
      As[nb][a_seg + 2][a_row] = rA.z; As[nb][a_seg + 3][a_row] = rA.w;
      if (c + 2 < NC) rA = *reinterpret_cast<const float4*>(Ag + (c + 2) * BK);
    }
    const int buf = c & 1;
#pragma unroll
    for (int k = 0; k < BK; k++) {
      ulonglong2 b01 = *reinterpret_cast<const ulonglong2*>(&Bs[buf][k][tc * 4]);
      ulonglong2 b23 = *reinterpret_cast<const ulonglong2*>(&Bs[buf][k][128 + tc * 4]);
      float4 a0 = *reinterpret_cast<const float4*>(&As[buf][k][tr * 8]);
      float4 a1 = *reinterpret_cast<const float4*>(&As[buf][k][tr * 8 + 4]);
      ull ap[8];
      ap[0] = pack2(a0.x); ap[1] = pack2(a0.y); ap[2] = pack2(a0.z); ap[3] = pack2(a0.w);
      ap[4] = pack2(a1.x); ap[5] = pack2(a1.y); ap[6] = pack2(a1.z); ap[7] = pack2(a1.w);
#pragma unroll
      for (int r = 0; r < 8; r++) {
        fma2(acc[r][0], ap[r], b01.x);
        fma2(acc[r][1], ap[r], b01.y);
        fma2(acc[r][2], ap[r], b23.x);
        fma2(acc[r][3], ap[r], b23.y);
      }
    }
  }
  const int c0 = tc * 4;
#pragma unroll
  for (int r = 0; r < 8; r++) {
    const int rr = rowBase + tr * 8 + r;
    float f[8];
    float2 v;
    v = unpack2(acc[r][0]); f[0] = v.x; f[1] = v.y;
    v = unpack2(acc[r][1]); f[2] = v.x; f[3] = v.y;
    v = unpack2(acc[r][2]); f[4] = v.x; f[5] = v.y;
    v = unpack2(acc[r][3]); f[6] = v.x; f[7] = v.y;
    float4 b0 = *reinterpret_cast<const float4*>(&bias[c0]);
    float4 b1 = *reinterpret_cast<const float4*>(&bias[128 + c0]);
    const size_t base0 = (size_t)rr * HID + c0;
    *reinterpret_cast<float4*>(&g_h[base0]) =
        make_float4(f[0] + b0.x, f[1] + b0.y, f[2] + b0.z, f[3] + b0.w);
    *reinterpret_cast<float4*>(&g_h[base0 + 128]) =
        make_float4(f[4] + b1.x, f[5] + b1.y, f[6] + b1.z, f[7] + b1.w);
  }
}

// ---- HMMA tensor GEMM: 128x256xK256, bf16 3-split/6-product, compacted ----
#define TG_PERM 0
#define TG_E    512
#define TG_A    8704    // 3 planes x 128 rows x 128B (SW128)
#define TG_B    57856   // 3 planes x 256 rows x 128B
#define TG_SMEM 156160

__device__ __forceinline__ void ldm_x4(uint32_t* r, uint32_t addr) {
  asm volatile("ldmatrix.sync.aligned.m8n8.x4.shared.b16 {%0,%1,%2,%3}, [%4];"
               : "=r"(r[0]), "=r"(r[1]), "=r"(r[2]), "=r"(r[3]) : "r"(addr));
}
__device__ __forceinline__ void ldm_x2(uint32_t* r, uint32_t addr) {
  asm volatile("ldmatrix.sync.aligned.m8n8.x2.shared.b16 {%0,%1}, [%2];"
               : "=r"(r[0]), "=r"(r[1]) : "r"(addr));
}
__device__ __forceinline__ void mma_bf16(float* d, const uint32_t* a, const uint32_t* b) {
  asm volatile(
    "mma.sync.aligned.m16n8k16.row.col.f32.bf16.bf16.f32 "
    "{%0,%1,%2,%3},{%4,%5,%6,%7},{%8,%9},{%0,%1,%2,%3};"
    : "+f"(d[0]), "+f"(d[1]), "+f"(d[2]), "+f"(d[3])
    : "r"(a[0]), "r"(a[1]), "r"(a[2]), "r"(a[3]), "r"(b[0]), "r"(b[1]));
}

// MODE 1: z = sigmoid(D+E_z); MODE 2: rh = sigmoid(D+E_r)*h; MODE 3: h = (1-z)h+z*tanh(D+E_h)
template <int MODE>
__global__ void __launch_bounds__(256, 1) tgemm_k(int t) {
  extern __shared__ __align__(16) unsigned char sm[];
  const int cnt = g_cnt[t];
  const int rowBase = blockIdx.x * 128;
  if (rowBase >= cnt) return;
  const int tid = threadIdx.x, wid = tid >> 5, lane = tid & 31;
  const uint32_t sb = smem_u32(sm);
  int* sPerm = (int*)(sm + TG_PERM);
  float* E8 = (float*)(sm + TG_E);
  if (tid < 128) {
    int j = rowBase + tid;
    sPerm[tid] = g_perm[t & 1][j < cnt ? j : rowBase];
  }
  for (int j = tid; j < 8 * HID; j += 256) E8[j] = g_E[MODE - 1][j >> 8][j & 255];

  const float* Asrc = (MODE == 3) ? g_rh : g_h;
  const __nv_bfloat16* Bsrc = &g_Wb[MODE - 1][0][0][0];
  const int wm = (wid >> 2) * 64, wn = (wid & 3) * 64;

  float acc[4][8][4];
#pragma unroll
  for (int mt = 0; mt < 4; mt++)
#pragma unroll
    for (int nt = 0; nt < 8; nt++)
#pragma unroll
      for (int q = 0; q < 4; q++) acc[mt][nt][q] = 0.f;

  for (int kc = 0; kc < 4; kc++) {
    __syncthreads();   // prev compute done; perm/E ready on kc==0
    // B: 3 planes x 256 rows x 4 units(16B) per chunk = 6144 units
#pragma unroll
    for (int i = 0; i < 24; i++) {
      int idx = tid + i * 256;
      int s = idx >> 11, rem = idx & 2047, n = rem >> 3, u = rem & 7;
      cp16(sm + TG_B + s * 32768 + n * 128 + ((u ^ (n & 7)) * 16),
           Bsrc + ((size_t)s * HID + n) * HID + kc * 64 + u * 8);
    }
    asm volatile("cp.async.commit_group;");
    // A: load f32, split3, store bf16 planes (swizzled)
#pragma unroll
    for (int i = 0; i < 8; i++) {
      int idx = tid + i * 256;
      int r = idx >> 4, q = idx & 15;
      float4 v = *reinterpret_cast<const float4*>(
          Asrc + (size_t)sPerm[r] * HID + kc * 64 + q * 4);
      __nv_bfloat16 s1[4], s2[4], s3[4];
      split3(v.x, s1[0], s2[0], s3[0]);
      split3(v.y, s1[1], s2[1], s3[1]);
      split3(v.z, s1[2], s2[2], s3[2]);
      split3(v.w, s1[3], s2[3], s3[3]);
      uint32_t off = r * 128 + (((q >> 1) ^ (r & 7)) * 16) + (q & 1) * 8;
      *reinterpret_cast<uint2*>(sm + TG_A + off) = make_uint2(bfpack(s1[0], s1[1]), bfpack(s1[2], s1[3]));
      *reinterpret_cast<uint2*>(sm + TG_A + 16384 + off) = make_uint2(bfpack(s2[0], s2[1]), bfpack(s2[2], s2[3]));
      *reinterpret_cast<uint2*>(sm + TG_A + 32768 + off) = make_uint2(bfpack(s3[0], s3[1]), bfpack(s3[2], s3[3]));
    }
    asm volatile("cp.async.wait_group 0;");
    __syncthreads();

    const int pa[6] = {0, 0, 1, 0, 2, 1};
    const int pb[6] = {0, 1, 0, 2, 0, 1};
#pragma unroll
    for (int p = 0; p < 6; p++) {
      const uint32_t aBase = sb + TG_A + pa[p] * 16384;
      const uint32_t bBase = sb + TG_B + pb[p] * 32768;
#pragma unroll
      for (int ks = 0; ks < 4; ks++) {
        uint32_t af[4][4], bf[8][2];
#pragma unroll
        for (int mt = 0; mt < 4; mt++) {
          int row = wm + mt * 16 + (lane & 15);
          int u = ks * 2 + (lane >> 4);
          ldm_x4(af[mt], aBase + row * 128 + ((u ^ (row & 7)) * 16));
        }
#pragma unroll
        for (int nt = 0; nt < 8; nt++) {
          int rn = wn + nt * 8 + (lane & 7);
          int u = ks * 2 + ((lane >> 3) & 1);
          ldm_x2(bf[nt], bBase + rn * 128 + ((u ^ (rn & 7)) * 16));
        }
#pragma unroll
        for (int mt = 0; mt < 4; mt++)
#pragma unroll
          for (int nt = 0; nt < 8; nt++)
            mma_bf16(acc[mt][nt], af[mt], bf[nt]);
      }
    }
  }

  // ---- epilogue: thread owns rows (lane>>2, +8) per mtile, col pairs ----
#pragma unroll
  for (int mt = 0; mt < 4; mt++) {
#pragma unroll
    for (int half = 0; half < 2; half++) {
      const int rl = wm + mt * 16 + (lane >> 2) + half * 8;
      if (rowBase + rl >= cnt) continue;
      const int grow = sPerm[rl];
      const float* Em = &E8[(g_state[grow] & 7) * HID];
      const int qo = half * 2;
#pragma unroll
      for (int nt = 0; nt < 8; nt++) {
        const int c = wn + nt * 8 + (lane & 3) * 2;
        float pre0 = acc[mt][nt][qo] + Em[c];
        float pre1 = acc[mt][nt][qo + 1] + Em[c + 1];
        const size_t b2 = (size_t)grow * HID + c;
        if (MODE == 1) {
          *reinterpret_cast<float2*>(&g_z[b2]) =
              make_float2(sigmoid_(pre0), sigmoid_(pre1));
        } else if (MODE == 2) {
          float2 h2 = *reinterpret_cast<const float2*>(&g_h[b2]);
          *reinterpret_cast<float2*>(&g_rh[b2]) =
              make_float2(sigmoid_(pre0) * h2.x, sigmoid_(pre1) * h2.y);
        } else {
          float2 z2 = *reinterpret_cast<const float2*>(&g_z[b2]);
          float2 h2 = *reinterpret_cast<const float2*>(&g_h[b2]);
          *reinterpret_cast<float2*>(&g_h[b2]) = make_float2(
              (1.f - z2.x) * h2.x + z2.x * xla_tanh(pre0),
              (1.f - z2.y) * h2.y + z2.y * xla_tanh(pre1));
        }
      }
    }
  }
}

// ---- sampler v2 + compaction (R8, unchanged) ----
__global__ void __launch_bounds__(256) sample_step(
    const float* __restrict__ W_out, const float* __restrict__ b_out,
    float* __restrict__ out, int t) {
  __shared__ float Ws[HID * VTOT];
  __shared__ float bs[8];
  __shared__ int wcnt[8], wpre[8], sbase;
  const int cnt = g_cnt[t];
  const int base_i = blockIdx.x * 64;
  if (base_i >= cnt) return;
  const int* perm = g_perm[t & 1];
  int* permN = g_perm[(t + 1) & 1];
  const int tid = threadIdx.x;
  for (int i = tid; i < HID * VTOT; i += 256) Ws[i] = W_out[i];
  if (tid < VTOT) bs[tid] = b_out[tid];
  __syncthreads();
  const int wid = tid >> 5, lane = tid & 31;
  const int g = lane & 3, rloc = lane >> 2;
  const int i = base_i + wid * 8 + rloc;
  const bool valid = (i < cnt);
  const int row = perm[valid ? i : base_i];
  const float* h = g_h + (size_t)row * HID + g * 64;
  float p[VTOT];
#pragma unroll
  for (int v = 0; v < VTOT; v++) p[v] = 0.f;
#pragma unroll
  for (int q = 0; q < 16; q++) {
    float4 hv = *reinterpret_cast<const float4*>(h + q * 4);
    const float* w = &Ws[(g * 64 + q * 4) * VTOT];
#pragma unroll
    for (int v = 0; v < VTOT; v++) {
      p[v] = fmaf(hv.x, w[v], p[v]);
      p[v] = fmaf(hv.y, w[VTOT + v], p[v]);
      p[v] = fmaf(hv.z, w[2 * VTOT + v], p[v]);
      p[v] = fmaf(hv.w, w[3 * VTOT + v], p[v]);
    }
  }
#pragma unroll
  for (int o = 1; o <= 2; o <<= 1)
#pragma unroll
    for (int v = 0; v < VTOT; v++) p[v] += __shfl_xor_sync(0xffffffffu, p[v], o);
  const uint32_t k0 = g_keyw[2 * t], k1 = g_keyw[2 * t + 1];
  float y_best = __int_as_float(0xff800000);
  int tok_best = 127;
  if (g < 3) {
#pragma unroll
    for (int j = 0; j < 2; j++) {
      const int v = 2 * g + j;
      uint32_t idx = (uint32_t)row * VTOT + v;
      uint32_t o0, o1;
      threefry2x32(k0, k1, 0u, idx, o0, o1);
      uint32_t bits = o0 ^ o1;
      uint32_t fb = (bits >> 9) | 0x3f800000u;
      float fu = __fadd_rn(__uint_as_float(fb), -1.0f);
      float u = fmaxf(1.17549435e-38f, fu);
      float gf = -__nv_logf(-__nv_logf(u));
      float y = (p[v] + bs[v]) + gf;
      if (y > y_best) { y_best = y; tok_best = v; }
    }
  }
#pragma unroll
  for (int o = 1; o <= 2; o <<= 1) {
    float y2 = __shfl_xor_sync(0xffffffffu, y_best, o);
    int t2 = __shfl_xor_sync(0xffffffffu, tok_best, o);
    if (y2 > y_best || (y2 == y_best && t2 < tok_best)) { y_best = y2; tok_best = t2; }
  }
  bool active_next = false;
  if (g == 0 && valid) {
    const int tok = tok_best;
    float logits[VTOT];
#pragma unroll
    for (int v = 0; v < VTOT; v++) logits[v] = p[v] + bs[v];
    float mx = logits[0];
#pragma unroll
    for (int v = 1; v < VTOT; v++) mx = fmaxf(mx, logits[v]);
    float ssum = 0.f;
#pragma unroll
    for (int v = 0; v < VTOT; v++)
      ssum = __fadd_rn(ssum, __nv_expf(__fadd_rn(logits[v], -mx)));
    float lp = (logits[tok] - mx) - __nv_logf(ssum);
    out[(size_t)row * 36 + t * VTOT + tok] = 1.f;
    out[(size_t)B_TOT * 36 + row] += lp;
    const bool is_stop = (tok == VTOT - 1);
    if (!is_stop) out[(size_t)B_TOT * 37 + row] += 1.f;
    g_state[row] = (unsigned char)(tok | (is_stop ? 8 : 0));
    active_next = !is_stop;
  }
  unsigned ballot = __ballot_sync(0xffffffffu, active_next);
  int warp_total = __popc(ballot);
  int rank = __popc(ballot & ((1u << lane) - 1u));
  if (lane == 0) wcnt[wid] = warp_total;
  __syncthreads();
  if (tid == 0) {
    int ssum = 0;
#pragma unroll
    for (int w = 0; w < 8; w++) { wpre[w] = ssum; ssum += wcnt[w]; }
    sbase = (ssum > 0) ? atomicAdd(&g_cnt[t + 1], ssum) : 0;
  }
  __syncthreads();
  if (active_next) permN[sbase + wpre[wid] + rank] = row;
}

// ---- launch ----
extern "C" void kernel_launch(void* const* d_in, const int* in_sizes, int n_in,
                              void* d_out, int out_size) {
  const float* x           = (const float*)d_in[0];
  const float* W_enc       = (const float*)d_in[1];
  const float* b_enc       = (const float*)d_in[2];
  const float* W_embed     = (const float*)d_in[3];
  const float* b_embed     = (const float*)d_in[4];
  const float* W_z         = (const float*)d_in[5];
  const float* b_z         = (const float*)d_in[6];
  const float* W_r         = (const float*)d_in[7];
  const float* b_r         = (const float*)d_in[8];
  const float* W_h         = (const float*)d_in[9];
  const float* b_h         = (const float*)d_in[10];
  const float* W_out       = (const float*)d_in[11];
  const float* b_out       = (const float*)d_in[12];
  const float* start_embed = (const float*)d_in[13];
  float* out = (float*)d_out;

  cudaFuncSetAttribute(tgemm_k<1>, cudaFuncAttributeMaxDynamicSharedMemorySize, TG_SMEM);
  cudaFuncSetAttribute(tgemm_k<2>, cudaFuncAttributeMaxDynamicSharedMemorySize, TG_SMEM);
  cudaFuncSetAttribute(tgemm_k<3>, cudaFuncAttributeMaxDynamicSharedMemorySize, TG_SMEM);

  init_kernel<<<B_TOT / 256, 256>>>(out);
  dim3 gE(8, 3);
  precompute_E<<<gE, 256>>>(W_embed, b_embed, W_z, b_z, W_r, b_r, W_h, b_h, start_embed);
  dim3 gW(256, 3);
  split_W<<<gW, 256>>>(W_z + HID * HID, W_r + HID * HID, W_h + HID * HID);

  enc_k<<<B_TOT / 64, 256>>>(x, W_enc, b_enc);

  const int TGRID = B_TOT / 128;
  for (int t = 0; t < TSTEPS; t++) {
    tgemm_k<1><<<TGRID, 256, TG_SMEM>>>(t);
    tgemm_k<2><<<TGRID, 256, TG_SMEM>>>(t);
    tgemm_k<3><<<TGRID, 256, TG_SMEM>>>(t);
    sample_step<<<B_TOT / 64, 256>>>(W_out, b_out, out, t);
  }
}

// round 12
// speedup vs baseline: 1.2159x; 1.2159x over previous
#include <cuda_runtime.h>
#include <cuda_fp16.h>
#include <cstdint>
#include <cstddef>
#include <math.h>

#define B_TOT 131072
#define D_IN 128
#define HID 256
#define VTOT 6
#define TSTEPS 6
typedef unsigned long long ull;

extern "C" __device__ float __nv_logf(float);
extern "C" __device__ float __nv_expf(float);

__device__ __align__(16) float g_h[(size_t)B_TOT * HID];
__device__ __align__(16) float g_z[(size_t)B_TOT * HID];
__device__ __align__(16) float g_rh[(size_t)B_TOT * HID];
__device__ unsigned char g_state[B_TOT];
__device__ __align__(16) float g_E[3][8][HID];
__device__ uint32_t g_keyw[12];
__device__ int g_perm[2][B_TOT];
__device__ int g_cnt[TSTEPS + 2];
__device__ __align__(16) __half g_Wh[3][2][HID][HID];  // [gate][split][n][k], W*32

__device__ __forceinline__ void threefry2x32(uint32_t k0, uint32_t k1,
                                             uint32_t c0, uint32_t c1,
                                             uint32_t& o0, uint32_t& o1) {
  uint32_t ks2 = k0 ^ k1 ^ 0x1BD11BDAu;
  uint32_t x0 = c0 + k0, x1 = c1 + k1;
#define TF_R(r) { x0 += x1; x1 = (x1 << (r)) | (x1 >> (32 - (r))); x1 ^= x0; }
  TF_R(13) TF_R(15) TF_R(26) TF_R(6)
  x0 += k1;  x1 += ks2 + 1u;
  TF_R(17) TF_R(29) TF_R(16) TF_R(24)
  x0 += ks2; x1 += k0 + 2u;
  TF_R(13) TF_R(15) TF_R(26) TF_R(6)
  x0 += k0;  x1 += k1 + 3u;
  TF_R(17) TF_R(29) TF_R(16) TF_R(24)
  x0 += k1;  x1 += ks2 + 4u;
  TF_R(13) TF_R(15) TF_R(26) TF_R(6)
  x0 += ks2; x1 += k0 + 5u;
#undef TF_R
  o0 = x0; o1 = x1;
}

__device__ __forceinline__ void fma2(ull& d, ull a, ull b) {
  asm("fma.rn.f32x2 %0, %1, %2, %0;" : "+l"(d) : "l"(a), "l"(b));
}
__device__ __forceinline__ ull pack2(float a) {
  ull r; asm("mov.b64 %0, {%1, %1};" : "=l"(r) : "f"(a)); return r;
}
__device__ __forceinline__ float2 unpack2(ull v) {
  float2 r; asm("mov.b64 {%0, %1}, %2;" : "=f"(r.x), "=f"(r.y) : "l"(v)); return r;
}
__device__ __forceinline__ void cp16(void* dst, const void* src) {
  unsigned d = (unsigned)__cvta_generic_to_shared(dst);
  asm volatile("cp.async.cg.shared.global [%0], [%1], 16;" :: "r"(d), "l"(src));
}
__device__ __forceinline__ uint32_t smem_u32(const void* p) {
  uint32_t a;
  asm("{ .reg .u64 t; cvta.to.shared.u64 t, %1; cvt.u32.u64 %0, t; }" : "=r"(a) : "l"(p));
  return a;
}
__device__ __forceinline__ float xla_tanh(float x) {
  float ax = fabsf(x);
  if (ax < 0.0004f) return x;
  float xc = fminf(fmaxf(x, -9.0f), 9.0f);
  float x2 = __fmul_rn(xc, xc);
  float num = -2.76076847742355e-16f;
  num = __fadd_rn(__fmul_rn(x2, num), 2.00018790482477e-13f);
  num = __fadd_rn(__fmul_rn(x2, num), -8.60467152213735e-11f);
  num = __fadd_rn(__fmul_rn(x2, num), 5.12229709037114e-08f);
  num = __fadd_rn(__fmul_rn(x2, num), 1.48572235717979e-05f);
  num = __fadd_rn(__fmul_rn(x2, num), 6.37261928875436e-04f);
  num = __fadd_rn(__fmul_rn(x2, num), 4.89352455891786e-03f);
  num = __fmul_rn(xc, num);
  float den = 1.19825839466702e-06f;
  den = __fadd_rn(__fmul_rn(x2, den), 1.18534705686654e-04f);
  den = __fadd_rn(__fmul_rn(x2, den), 2.26843463243900e-03f);
  den = __fadd_rn(__fmul_rn(x2, den), 4.89352518554385e-03f);
  return __fdiv_rn(num, den);
}
__device__ __forceinline__ float sigmoid_(float x) {
  return __fadd_rn(0.5f, __fmul_rn(0.5f, xla_tanh(__fmul_rn(0.5f, x))));
}
__device__ __forceinline__ void split2h(float x, __half& h1, __half& h2) {
  h1 = __float2half_rn(x);
  h2 = __float2half_rn(__fadd_rn(x, -__half2float(h1)));
}
__device__ __forceinline__ uint32_t hpack(__half a, __half b) {
  __half2 v(a, b);
  return reinterpret_cast<uint32_t&>(v);
}

// ---- init ----
__global__ void init_kernel(float* __restrict__ out) {
  const int gid = blockIdx.x * blockDim.x + threadIdx.x;
  const int nthr = gridDim.x * blockDim.x;
  for (size_t j = gid; j < (size_t)B_TOT * 36; j += nthr) out[j] = 0.f;
  if (gid < B_TOT) {
    out[(size_t)B_TOT * 36 + gid] = 0.f;
    out[(size_t)B_TOT * 37 + gid] = 0.f;
    g_state[gid] = 7;
    g_perm[0][gid] = gid;
  }
  if (gid < TSTEPS + 2) g_cnt[gid] = (gid == 0) ? B_TOT : 0;
  if (gid < 6) {
    uint32_t a, b;
    threefry2x32(0u, 42u, 0u, (uint32_t)gid, a, b);
    g_keyw[2 * gid] = a; g_keyw[2 * gid + 1] = b;
  }
}

__global__ void precompute_E(const float* __restrict__ W_embed,
                             const float* __restrict__ b_embed,
                             const float* __restrict__ Wz, const float* __restrict__ bz,
                             const float* __restrict__ Wr, const float* __restrict__ br,
                             const float* __restrict__ Wh, const float* __restrict__ bh,
                             const float* __restrict__ start_embed) {
  int s = blockIdx.x, m = blockIdx.y, j = threadIdx.x;
  const float* W  = (m == 0) ? Wz : (m == 1) ? Wr : Wh;
  const float* bb = (m == 0) ? bz : (m == 1) ? br : bh;
  float acc = bb[j];
  for (int k = 0; k < HID; k++) {
    float e;
    if (s == 7) e = start_embed[k];
    else { e = b_embed[k]; if (s < 6) e += W_embed[s * HID + k]; }
    acc = fmaf(e, W[k * HID + j], acc);
  }
  g_E[m][s][j] = acc;
}

// weights * 32, fp16 2-term split, [n][k] (col-major for row.col mma)
__global__ void split_W(const float* __restrict__ Wz, const float* __restrict__ Wr,
                        const float* __restrict__ Wh) {
  const int n = blockIdx.x, m = blockIdx.y, k = threadIdx.x;
  const float* W = (m == 0) ? Wz : (m == 1) ? Wr : Wh;  // bottom 256 rows, [k][n]
  __half h1, h2;
  split2h(W[(size_t)k * HID + n] * 32.0f, h1, h2);
  g_Wh[m][0][n][k] = h1; g_Wh[m][1][n][k] = h2;
}

// ---- encoder: R8 FFMA2 core ----
__global__ void __launch_bounds__(256, 2) enc_k(
    const float* __restrict__ A, const float* __restrict__ Bw,
    const float* __restrict__ bias) {
  constexpr int BM = 64, BN = 256, BK = 16, APAD = BM + 4;
  __shared__ __align__(16) float As[2][BK][APAD];
  __shared__ __align__(16) float Bs[2][BK][BN];
  const int rowBase = blockIdx.x * BM;
  const int tid = threadIdx.x, tc = tid & 31, tr = tid >> 5;
  const int a_row = tid >> 2, a_seg = (tid & 3) << 2;
  const float* Ag = A + (size_t)(rowBase + a_row) * D_IN + a_seg;
  ull acc[8][4];
#pragma unroll
  for (int r = 0; r < 8; r++)
#pragma unroll
    for (int p = 0; p < 4; p++) acc[r][p] = 0ull;
  const int NC = D_IN / BK;
  float4 rA = *reinterpret_cast<const float4*>(Ag);
#pragma unroll
  for (int i = 0; i < 4; i++) {
    int idx = tid + i * 256, kr = idx >> 6, cs = (idx & 63) << 2;
    cp16(&Bs[0][kr][cs], Bw + (size_t)kr * BN + cs);
  }
  asm volatile("cp.async.commit_group;");
  As[0][a_seg][a_row] = rA.x; As[0][a_seg + 1][a_row] = rA.y;
  As[0][a_seg + 2][a_row] = rA.z; As[0][a_seg + 3][a_row] = rA.w;
  rA = *reinterpret_cast<const float4*>(Ag + BK);
  for (int c = 0; c < NC; c++) {
    asm volatile("cp.async.wait_group 0;");
    __syncthreads();
    if (c + 1 < NC) {
      const int nb = (c + 1) & 1;
#pragma unroll
      for (int i = 0; i < 4; i++) {
        int idx = tid + i * 256, kr = idx >> 6, cs = (idx & 63) << 2;
        cp16(&Bs[nb][kr][cs], Bw + (size_t)((c + 1) * BK + kr) * BN + cs);
      }
      asm volatile("cp.async.commit_group;");
      As[nb][a_seg][a_row] = rA.x; As[nb][a_seg + 1][a_row] = rA.y;
      As[nb][a_seg + 2][a_row] = rA.z; As[nb][a_seg + 3][a_row] = rA.w;
      if (c + 2 < NC) rA = *reinterpret_cast<const float4*>(Ag + (c + 2) * BK);
    }
    const int buf = c & 1;
#pragma unroll
    for (int k = 0; k < BK; k++) {
      ulonglong2 b01 = *reinterpret_cast<const ulonglong2*>(&Bs[buf][k][tc * 4]);
      ulonglong2 b23 = *reinterpret_cast<const ulonglong2*>(&Bs[buf][k][128 + tc * 4]);
      float4 a0 = *reinterpret_cast<const float4*>(&As[buf][k][tr * 8]);
      float4 a1 = *reinterpret_cast<const float4*>(&As[buf][k][tr * 8 + 4]);
      ull ap[8];
      ap[0] = pack2(a0.x); ap[1] = pack2(a0.y); ap[2] = pack2(a0.z); ap[3] = pack2(a0.w);
      ap[4] = pack2(a1.x); ap[5] = pack2(a1.y); ap[6] = pack2(a1.z); ap[7] = pack2(a1.w);
#pragma unroll
      for (int r = 0; r < 8; r++) {
        fma2(acc[r][0], ap[r], b01.x);
        fma2(acc[r][1], ap[r], b01.y);
        fma2(acc[r][2], ap[r], b23.x);
        fma2(acc[r][3], ap[r], b23.y);
      }
    }
  }
  const int c0 = tc * 4;
#pragma unroll
  for (int r = 0; r < 8; r++) {
    const int rr = rowBase + tr * 8 + r;
    float f[8];
    float2 v;
    v = unpack2(acc[r][0]); f[0] = v.x; f[1] = v.y;
    v = unpack2(acc[r][1]); f[2] = v.x; f[3] = v.y;
    v = unpack2(acc[r][2]); f[4] = v.x; f[5] = v.y;
    v = unpack2(acc[r][3]); f[6] = v.x; f[7] = v.y;
    float4 b0 = *reinterpret_cast<const float4*>(&bias[c0]);
    float4 b1 = *reinterpret_cast<const float4*>(&bias[128 + c0]);
    const size_t base0 = (size_t)rr * HID + c0;
    *reinterpret_cast<float4*>(&g_h[base0]) =
        make_float4(f[0] + b0.x, f[1] + b0.y, f[2] + b0.z, f[3] + b0.w);
    *reinterpret_cast<float4*>(&g_h[base0 + 128]) =
        make_float4(f[4] + b1.x, f[5] + b1.y, f[6] + b1.z, f[7] + b1.w);
  }
}

// ---- HMMA tensor GEMM v2: fp16 2-split/3-product, double-buffered ----
#define TG_PERM 0
#define TG_E    512
#define TG_A    8704    // [2buf][2pl][128][128B]
#define TG_B    74240   // [2buf][2pl][256][128B]
#define TG_SMEM 205312

__device__ __forceinline__ void ldm_x4(uint32_t* r, uint32_t addr) {
  asm volatile("ldmatrix.sync.aligned.m8n8.x4.shared.b16 {%0,%1,%2,%3}, [%4];"
               : "=r"(r[0]), "=r"(r[1]), "=r"(r[2]), "=r"(r[3]) : "r"(addr));
}
__device__ __forceinline__ void ldm_x2(uint32_t* r, uint32_t addr) {
  asm volatile("ldmatrix.sync.aligned.m8n8.x2.shared.b16 {%0,%1}, [%2];"
               : "=r"(r[0]), "=r"(r[1]) : "r"(addr));
}
__device__ __forceinline__ void mma_f16(float* d, const uint32_t* a, const uint32_t* b) {
  asm volatile(
    "mma.sync.aligned.m16n8k16.row.col.f32.f16.f16.f32 "
    "{%0,%1,%2,%3},{%4,%5,%6,%7},{%8,%9},{%0,%1,%2,%3};"
    : "+f"(d[0]), "+f"(d[1]), "+f"(d[2]), "+f"(d[3])
    : "r"(a[0]), "r"(a[1]), "r"(a[2]), "r"(a[3]), "r"(b[0]), "r"(b[1]));
}

template <int MODE>
__device__ __forceinline__ void tg_stage(unsigned char* sm, int kc, int buf,
                                         const float* Asrc, const __half* Bsrc,
                                         const int* sPerm, int tid) {
  // B: 2 planes x 256 rows x 8 16B-units = 4096 cp.async
#pragma unroll
  for (int i = 0; i < 16; i++) {
    int idx = tid + i * 256;
    int s = idx >> 11, rem = idx & 2047, n = rem >> 3, u = rem & 7;
    cp16(sm + TG_B + buf * 65536 + s * 32768 + n * 128 + ((u ^ (n & 7)) * 16),
         Bsrc + ((size_t)s * HID + n) * HID + kc * 64 + u * 8);
  }
  asm volatile("cp.async.commit_group;");
  // A: LDG f32, split2h, STS both planes
#pragma unroll
  for (int i = 0; i < 8; i++) {
    int idx = tid + i * 256;
    int r = idx >> 4, q = idx & 15;
    float4 v = *reinterpret_cast<const float4*>(
        Asrc + (size_t)sPerm[r] * HID + kc * 64 + q * 4);
    __half s1[4], s2[4];
    split2h(v.x, s1[0], s2[0]); split2h(v.y, s1[1], s2[1]);
    split2h(v.z, s1[2], s2[2]); split2h(v.w, s1[3], s2[3]);
    uint32_t off = r * 128 + (((q >> 1) ^ (r & 7)) * 16) + (q & 1) * 8;
    *reinterpret_cast<uint2*>(sm + TG_A + buf * 32768 + off) =
        make_uint2(hpack(s1[0], s1[1]), hpack(s1[2], s1[3]));
    *reinterpret_cast<uint2*>(sm + TG_A + buf * 32768 + 16384 + off) =
        make_uint2(hpack(s2[0], s2[1]), hpack(s2[2], s2[3]));
  }
}

// MODE 1: z=sig(D/32+E); MODE 2: rh=sig(D/32+E)*h; MODE 3: h=(1-z)h+z*tanh(D/32+E)
template <int MODE>
__global__ void __launch_bounds__(256, 1) tgemm_k(int t) {
  extern __shared__ __align__(16) unsigned char sm[];
  const int cnt = g_cnt[t];
  const int rowBase = blockIdx.x * 128;
  if (rowBase >= cnt) return;
  const int tid = threadIdx.x, wid = tid >> 5, lane = tid & 31;
  const uint32_t sb = smem_u32(sm);
  int* sPerm = (int*)(sm + TG_PERM);
  float* E8 = (float*)(sm + TG_E);
  if (tid < 128) {
    int j = rowBase + tid;
    sPerm[tid] = g_perm[t & 1][j < cnt ? j : rowBase];
  }
  for (int j = tid; j < 8 * HID; j += 256) E8[j] = g_E[MODE - 1][j >> 8][j & 255];
  __syncthreads();   // perm visible before stage uses it

  const float* Asrc = (MODE == 3) ? g_rh : g_h;
  const __half* Bsrc = &g_Wh[MODE - 1][0][0][0];
  const int wm = (wid >> 2) * 64, wn = (wid & 3) * 64;

  float acc[4][8][4];
#pragma unroll
  for (int mt = 0; mt < 4; mt++)
#pragma unroll
    for (int nt = 0; nt < 8; nt++)
#pragma unroll
      for (int q = 0; q < 4; q++) acc[mt][nt][q] = 0.f;

  tg_stage<MODE>(sm, 0, 0, Asrc, Bsrc, sPerm, tid);
  asm volatile("cp.async.wait_group 0;");
  __syncthreads();

  for (int kc = 0; kc < 4; kc++) {
    const int buf = kc & 1;
    if (kc < 3) tg_stage<MODE>(sm, kc + 1, buf ^ 1, Asrc, Bsrc, sPerm, tid);
    const uint32_t aB = sb + TG_A + buf * 32768;
    const uint32_t bB = sb + TG_B + buf * 65536;
#pragma unroll
    for (int ks = 0; ks < 4; ks++) {
      uint32_t af[2][4][4];
#pragma unroll
      for (int pl = 0; pl < 2; pl++)
#pragma unroll
        for (int mt = 0; mt < 4; mt++) {
          int row = wm + mt * 16 + (lane & 15);
          int u = ks * 2 + (lane >> 4);
          ldm_x4(af[pl][mt], aB + pl * 16384 + row * 128 + ((u ^ (row & 7)) * 16));
        }
#pragma unroll
      for (int nt = 0; nt < 8; nt++) {
        uint32_t bf[2][2];
#pragma unroll
        for (int pl = 0; pl < 2; pl++) {
          int rn = wn + nt * 8 + (lane & 7);
          int u = ks * 2 + ((lane >> 3) & 1);
          ldm_x2(bf[pl], bB + pl * 32768 + rn * 128 + ((u ^ (rn & 7)) * 16));
        }
#pragma unroll
        for (int mt = 0; mt < 4; mt++) {
          mma_f16(acc[mt][nt], af[0][mt], bf[0]);  // a1*b1
          mma_f16(acc[mt][nt], af[0][mt], bf[1]);  // a1*b2
          mma_f16(acc[mt][nt], af[1][mt], bf[0]);  // a2*b1
        }
      }
    }
    if (kc < 3) {
      asm volatile("cp.async.wait_group 0;");
      __syncthreads();
    }
  }

  // ---- epilogue ----
#pragma unroll
  for (int mt = 0; mt < 4; mt++) {
#pragma unroll
    for (int half = 0; half < 2; half++) {
      const int rl = wm + mt * 16 + (lane >> 2) + half * 8;
      if (rowBase + rl >= cnt) continue;
      const int grow = sPerm[rl];
      const float* Em = &E8[(g_state[grow] & 7) * HID];
      const int qo = half * 2;
#pragma unroll
      for (int nt = 0; nt < 8; nt++) {
        const int c = wn + nt * 8 + (lane & 3) * 2;
        float pre0 = __fadd_rn(__fmul_rn(acc[mt][nt][qo], 0.03125f), Em[c]);
        float pre1 = __fadd_rn(__fmul_rn(acc[mt][nt][qo + 1], 0.03125f), Em[c + 1]);
        const size_t b2 = (size_t)grow * HID + c;
        if (MODE == 1) {
          *reinterpret_cast<float2*>(&g_z[b2]) =
              make_float2(sigmoid_(pre0), sigmoid_(pre1));
        } else if (MODE == 2) {
          float2 h2 = *reinterpret_cast<const float2*>(&g_h[b2]);
          *reinterpret_cast<float2*>(&g_rh[b2]) =
              make_float2(sigmoid_(pre0) * h2.x, sigmoid_(pre1) * h2.y);
        } else {
          float2 z2 = *reinterpret_cast<const float2*>(&g_z[b2]);
          float2 h2 = *reinterpret_cast<const float2*>(&g_h[b2]);
          *reinterpret_cast<float2*>(&g_h[b2]) = make_float2(
              (1.f - z2.x) * h2.x + z2.x * xla_tanh(pre0),
              (1.f - z2.y) * h2.y + z2.y * xla_tanh(pre1));
        }
      }
    }
  }
}

// ---- sampler v2 + compaction (R8, unchanged) ----
__global__ void __launch_bounds__(256) sample_step(
    const float* __restrict__ W_out, const float* __restrict__ b_out,
    float* __restrict__ out, int t) {
  __shared__ float Ws[HID * VTOT];
  __shared__ float bs[8];
  __shared__ int wcnt[8], wpre[8], sbase;
  const int cnt = g_cnt[t];
  const int base_i = blockIdx.x * 64;
  if (base_i >= cnt) return;
  const int* perm = g_perm[t & 1];
  int* permN = g_perm[(t + 1) & 1];
  const int tid = threadIdx.x;
  for (int i = tid; i < HID * VTOT; i += 256) Ws[i] = W_out[i];
  if (tid < VTOT) bs[tid] = b_out[tid];
  __syncthreads();
  const int wid = tid >> 5, lane = tid & 31;
  const int g = lane & 3, rloc = lane >> 2;
  const int i = base_i + wid * 8 + rloc;
  const bool valid = (i < cnt);
  const int row = perm[valid ? i : base_i];
  const float* h = g_h + (size_t)row * HID + g * 64;
  float p[VTOT];
#pragma unroll
  for (int v = 0; v < VTOT; v++) p[v] = 0.f;
#pragma unroll
  for (int q = 0; q < 16; q++) {
    float4 hv = *reinterpret_cast<const float4*>(h + q * 4);
    const float* w = &Ws[(g * 64 + q * 4) * VTOT];
#pragma unroll
    for (int v = 0; v < VTOT; v++) {
      p[v] = fmaf(hv.x, w[v], p[v]);
      p[v] = fmaf(hv.y, w[VTOT + v], p[v]);
      p[v] = fmaf(hv.z, w[2 * VTOT + v], p[v]);
      p[v] = fmaf(hv.w, w[3 * VTOT + v], p[v]);
    }
  }
#pragma unroll
  for (int o = 1; o <= 2; o <<= 1)
#pragma unroll
    for (int v = 0; v < VTOT; v++) p[v] += __shfl_xor_sync(0xffffffffu, p[v], o);
  const uint32_t k0 = g_keyw[2 * t], k1 = g_keyw[2 * t + 1];
  float y_best = __int_as_float(0xff800000);
  int tok_best = 127;
  if (g < 3) {
#pragma unroll
    for (int j = 0; j < 2; j++) {
      const int v = 2 * g + j;
      uint32_t idx = (uint32_t)row * VTOT + v;
      uint32_t o0, o1;
      threefry2x32(k0, k1, 0u, idx, o0, o1);
      uint32_t bits = o0 ^ o1;
      uint32_t fb = (bits >> 9) | 0x3f800000u;
      float fu = __fadd_rn(__uint_as_float(fb), -1.0f);
      float u = fmaxf(1.17549435e-38f, fu);
      float gf = -__nv_logf(-__nv_logf(u));
      float y = (p[v] + bs[v]) + gf;
      if (y > y_best) { y_best = y; tok_best = v; }
    }
  }
#pragma unroll
  for (int o = 1; o <= 2; o <<= 1) {
    float y2 = __shfl_xor_sync(0xffffffffu, y_best, o);
    int t2 = __shfl_xor_sync(0xffffffffu, tok_best, o);
    if (y2 > y_best || (y2 == y_best && t2 < tok_best)) { y_best = y2; tok_best = t2; }
  }
  bool active_next = false;
  if (g == 0 && valid) {
    const int tok = tok_best;
    float logits[VTOT];
#pragma unroll
    for (int v = 0; v < VTOT; v++) logits[v] = p[v] + bs[v];
    float mx = logits[0];
#pragma unroll
    for (int v = 1; v < VTOT; v++) mx = fmaxf(mx, logits[v]);
    float ssum = 0.f;
#pragma unroll
    for (int v = 0; v < VTOT; v++)
      ssum = __fadd_rn(ssum, __nv_expf(__fadd_rn(logits[v], -mx)));
    float lp = (logits[tok] - mx) - __nv_logf(ssum);
    out[(size_t)row * 36 + t * VTOT + tok] = 1.f;
    out[(size_t)B_TOT * 36 + row] += lp;
    const bool is_stop = (tok == VTOT - 1);
    if (!is_stop) out[(size_t)B_TOT * 37 + row] += 1.f;
    g_state[row] = (unsigned char)(tok | (is_stop ? 8 : 0));
    active_next = !is_stop;
  }
  unsigned ballot = __ballot_sync(0xffffffffu, active_next);
  int warp_total = __popc(ballot);
  int rank = __popc(ballot & ((1u << lane) - 1u));
  if (lane == 0) wcnt[wid] = warp_total;
  __syncthreads();
  if (tid == 0) {
    int ssum = 0;
#pragma unroll
    for (int w = 0; w < 8; w++) { wpre[w] = ssum; ssum += wcnt[w]; }
    sbase = (ssum > 0) ? atomicAdd(&g_cnt[t + 1], ssum) : 0;
  }
  __syncthreads();
  if (active_next) permN[sbase + wpre[wid] + rank] = row;
}

// ---- launch ----
extern "C" void kernel_launch(void* const* d_in, const int* in_sizes, int n_in,
                              void* d_out, int out_size) {
  const float* x           = (const float*)d_in[0];
  const float* W_enc       = (const float*)d_in[1];
  const float* b_enc       = (const float*)d_in[2];
  const float* W_embed     = (const float*)d_in[3];
  const float* b_embed     = (const float*)d_in[4];
  const float* W_z         = (const float*)d_in[5];
  const float* b_z         = (const float*)d_in[6];
  const float* W_r         = (const float*)d_in[7];
  const float* b_r         = (const float*)d_in[8];
  const float* W_h         = (const float*)d_in[9];
  const float* b_h         = (const float*)d_in[10];
  const float* W_out       = (const float*)d_in[11];
  const float* b_out       = (const float*)d_in[12];
  const float* start_embed = (const float*)d_in[13];
  float* out = (float*)d_out;

  cudaFuncSetAttribute(tgemm_k<1>, cudaFuncAttributeMaxDynamicSharedMemorySize, TG_SMEM);
  cudaFuncSetAttribute(tgemm_k<2>, cudaFuncAttributeMaxDynamicSharedMemorySize, TG_SMEM);
  cudaFuncSetAttribute(tgemm_k<3>, cudaFuncAttributeMaxDynamicSharedMemorySize, TG_SMEM);

  init_kernel<<<B_TOT / 256, 256>>>(out);
  dim3 gE(8, 3);
  precompute_E<<<gE, 256>>>(W_embed, b_embed, W_z, b_z, W_r, b_r, W_h, b_h, start_embed);
  dim3 gW(256, 3);
  split_W<<<gW, 256>>>(W_z + HID * HID, W_r + HID * HID, W_h + HID * HID);

  enc_k<<<B_TOT / 64, 256>>>(x, W_enc, b_enc);

  const int TGRID = B_TOT / 128;
  for (int t = 0; t < TSTEPS; t++) {
    tgemm_k<1><<<TGRID, 256, TG_SMEM>>>(t);
    tgemm_k<2><<<TGRID, 256, TG_SMEM>>>(t);
    tgemm_k<3><<<TGRID, 256, TG_SMEM>>>(t);
    sample_step<<<B_TOT / 64, 256>>>(W_out, b_out, out, t);
  }
}

// round 13
// speedup vs baseline: 2.6834x; 2.2069x over previous
#include <cuda_runtime.h>
#include <cstdint>
#include <cstddef>
#include <math.h>

#define B_TOT 131072
#define D_IN  128
#define HID   256
#define VTOT  6
#define TSTEPS 6

typedef unsigned long long ull;

extern "C" __device__ float __nv_logf(float);
extern "C" __device__ float __nv_expf(float);

// ---------------- persistent device scratch ---------------------------------
__device__ __align__(16) float g_h [(size_t)B_TOT * HID];
__device__ __align__(16) float g_z [(size_t)B_TOT * HID];
__device__ __align__(16) float g_rh[(size_t)B_TOT * HID];
__device__ unsigned char g_state[B_TOT];
__device__ __align__(16) float g_E[3][8][HID];
__device__ uint32_t g_keyw[12];
__device__ int g_perm[2][B_TOT];
__device__ int g_cnt[TSTEPS + 2];

// ---------------- threefry2x32 (exact JAX schedule) -------------------------
__device__ __forceinline__ void threefry2x32(uint32_t k0, uint32_t k1,
                                             uint32_t c0, uint32_t c1,
                                             uint32_t& o0, uint32_t& o1) {
  uint32_t ks2 = k0 ^ k1 ^ 0x1BD11BDAu;
  uint32_t x0 = c0 + k0, x1 = c1 + k1;
#define TF_R(r) { x0 += x1; x1 = (x1 << (r)) | (x1 >> (32 - (r))); x1 ^= x0; }
  TF_R(13) TF_R(15) TF_R(26) TF_R(6)
  x0 += k1;  x1 += ks2 + 1u;
  TF_R(17) TF_R(29) TF_R(16) TF_R(24)
  x0 += ks2; x1 += k0 + 2u;
  TF_R(13) TF_R(15) TF_R(26) TF_R(6)
  x0 += k0;  x1 += k1 + 3u;
  TF_R(17) TF_R(29) TF_R(16) TF_R(24)
  x0 += k1;  x1 += ks2 + 4u;
  TF_R(13) TF_R(15) TF_R(26) TF_R(6)
  x0 += ks2; x1 += k0 + 5u;
#undef TF_R
  o0 = x0; o1 = x1;
}

// ---------------- helpers -----------------------------------------------------
__device__ __forceinline__ void fma2(ull& d, ull a, ull b) {
  asm("fma.rn.f32x2 %0, %1, %2, %0;" : "+l"(d) : "l"(a), "l"(b));
}
__device__ __forceinline__ ull pack2(float a) {
  ull r; asm("mov.b64 %0, {%1, %1};" : "=l"(r) : "f"(a)); return r;
}
__device__ __forceinline__ float2 unpack2(ull v) {
  float2 r; asm("mov.b64 {%0, %1}, %2;" : "=f"(r.x), "=f"(r.y) : "l"(v)); return r;
}
__device__ __forceinline__ void cp16(void* dst, const void* src) {
  unsigned d = (unsigned)__cvta_generic_to_shared(dst);
  asm volatile("cp.async.cg.shared.global [%0], [%1], 16;" :: "r"(d), "l"(src));
}
__device__ __forceinline__ float xla_tanh(float x) {
  float ax = fabsf(x);
  if (ax < 0.0004f) return x;
  float xc = fminf(fmaxf(x, -9.0f), 9.0f);
  float x2 = __fmul_rn(xc, xc);
  float num = -2.76076847742355e-16f;
  num = __fadd_rn(__fmul_rn(x2, num), 2.00018790482477e-13f);
  num = __fadd_rn(__fmul_rn(x2, num), -8.60467152213735e-11f);
  num = __fadd_rn(__fmul_rn(x2, num), 5.12229709037114e-08f);
  num = __fadd_rn(__fmul_rn(x2, num), 1.48572235717979e-05f);
  num = __fadd_rn(__fmul_rn(x2, num), 6.37261928875436e-04f);
  num = __fadd_rn(__fmul_rn(x2, num), 4.89352455891786e-03f);
  num = __fmul_rn(xc, num);
  float den = 1.19825839466702e-06f;
  den = __fadd_rn(__fmul_rn(x2, den), 1.18534705686654e-04f);
  den = __fadd_rn(__fmul_rn(x2, den), 2.26843463243900e-03f);
  den = __fadd_rn(__fmul_rn(x2, den), 4.89352518554385e-03f);
  return __fdiv_rn(num, den);
}
__device__ __forceinline__ float sigmoid_(float x) {
  return __fadd_rn(0.5f, __fmul_rn(0.5f, xla_tanh(__fmul_rn(0.5f, x))));
}

// ---------------- init --------------------------------------------------------
__global__ void init_kernel(float* __restrict__ out) {
  const int gid = blockIdx.x * blockDim.x + threadIdx.x;
  const int nthr = gridDim.x * blockDim.x;
  for (size_t j = gid; j < (size_t)B_TOT * 36; j += nthr) out[j] = 0.f;
  if (gid < B_TOT) {
    out[(size_t)B_TOT * 36 + gid] = 0.f;
    out[(size_t)B_TOT * 37 + gid] = 0.f;
    g_state[gid] = 7;
    g_perm[0][gid] = gid;
  }
  if (gid < TSTEPS + 2) g_cnt[gid] = (gid == 0) ? B_TOT : 0;
  if (gid < 6) {
    uint32_t a, b;
    threefry2x32(0u, 42u, 0u, (uint32_t)gid, a, b);
    g_keyw[2 * gid]     = a;
    g_keyw[2 * gid + 1] = b;
  }
}

// ---------------- precompute E tables ----------------------------------------
__global__ void precompute_E(const float* __restrict__ W_embed,
                             const float* __restrict__ b_embed,
                             const float* __restrict__ Wz, const float* __restrict__ bz,
                             const float* __restrict__ Wr, const float* __restrict__ br,
                             const float* __restrict__ Wh, const float* __restrict__ bh,
                             const float* __restrict__ start_embed) {
  int s = blockIdx.x, m = blockIdx.y, j = threadIdx.x;
  const float* W  = (m == 0) ? Wz : (m == 1) ? Wr : Wh;
  const float* bb = (m == 0) ? bz : (m == 1) ? br : bh;
  float acc = bb[j];
  for (int k = 0; k < HID; k++) {
    float e;
    if (s == 7) e = start_embed[k];
    else { e = b_embed[k]; if (s < 6) e += W_embed[s * HID + k]; }
    acc = fmaf(e, W[k * HID + j], acc);
  }
  g_E[m][s][j] = acc;
}

// ---------------- fused GEMM, BK=32, compacted rows ---------------------------
// dyn smem: As[2][32][68]f =17408B | Bs[2][32][256]f =65536B | sPerm[64] =256B
#define GSM_AS 0
#define GSM_BS 17408
#define GSM_PERM 82944
#define GSM_TOTAL 83200

template <int MODE>
__global__ void __launch_bounds__(256, 2) gemm_k(
    const float* __restrict__ Aext, int lda, int K,
    const float* __restrict__ Bw, const float* __restrict__ bias, int t) {
  constexpr int BM = 64, BN = 256, BK = 32, APAD = BM + 4;
  extern __shared__ __align__(16) unsigned char smraw[];
  float (*As)[BK][APAD] = reinterpret_cast<float(*)[BK][APAD]>(smraw + GSM_AS);
  float (*Bs)[BK][BN]   = reinterpret_cast<float(*)[BK][BN]>(smraw + GSM_BS);
  int* sPerm            = reinterpret_cast<int*>(smraw + GSM_PERM);

  const int rowBase = blockIdx.x * BM;
  int cnt = B_TOT;
  if (MODE != 0) {
    cnt = g_cnt[t];
    if (rowBase >= cnt) return;
    const int* perm = g_perm[t & 1];
    if (threadIdx.x < BM) {
      int j = rowBase + threadIdx.x;
      sPerm[threadIdx.x] = perm[j < cnt ? j : rowBase];
    }
    __syncthreads();
  }

  const float* A = (MODE == 0) ? Aext : (MODE == 3 ? g_rh : g_h);
  const int tid = threadIdx.x;
  const int tc = tid & 31;
  const int tr = tid >> 5;

  const int a_row = tid >> 2;          // 0..63
  const int a_seg = (tid & 3) << 2;    // 0,4,8,12  (k-offsets a_seg and a_seg+16)
  const int arow_g = (MODE == 0) ? (rowBase + a_row) : sPerm[a_row];
  const float* Ag = A + (size_t)arow_g * lda + a_seg;

  ull acc[8][4];
#pragma unroll
  for (int r = 0; r < 8; r++)
#pragma unroll
    for (int p = 0; p < 4; p++) acc[r][p] = 0ull;

  const int NC = K / BK;

  // ---- prologue: stage chunk 0 ----
  float4 rA0 = *reinterpret_cast<const float4*>(Ag);
  float4 rA1 = *reinterpret_cast<const float4*>(Ag + 16);
#pragma unroll
  for (int i = 0; i < 8; i++) {
    int idx = tid + i * 256;
    int kr = idx >> 6;             // 0..31
    int cs = (idx & 63) << 2;      // 0..252
    cp16(&Bs[0][kr][cs], Bw + (size_t)kr * BN + cs);
  }
  asm volatile("cp.async.commit_group;");
#pragma unroll
  for (int j = 0; j < 4; j++) {
    As[0][a_seg + j][a_row]      = (&rA0.x)[j];
    As[0][a_seg + 16 + j][a_row] = (&rA1.x)[j];
  }
  if (NC > 1) {
    rA0 = *reinterpret_cast<const float4*>(Ag + BK);
    rA1 = *reinterpret_cast<const float4*>(Ag + BK + 16);
  }

  for (int c = 0; c < NC; c++) {
    asm volatile("cp.async.wait_group 0;");
    __syncthreads();
    if (c + 1 < NC) {
      const int nbuf = (c + 1) & 1;
#pragma unroll
      for (int i = 0; i < 8; i++) {
        int idx = tid + i * 256;
        int kr = idx >> 6;
        int cs = (idx & 63) << 2;
        cp16(&Bs[nbuf][kr][cs], Bw + (size_t)((c + 1) * BK + kr) * BN + cs);
      }
      asm volatile("cp.async.commit_group;");
#pragma unroll
      for (int j = 0; j < 4; j++) {
        As[nbuf][a_seg + j][a_row]      = (&rA0.x)[j];
        As[nbuf][a_seg + 16 + j][a_row] = (&rA1.x)[j];
      }
      if (c + 2 < NC) {
        rA0 = *reinterpret_cast<const float4*>(Ag + (c + 2) * BK);
        rA1 = *reinterpret_cast<const float4*>(Ag + (c + 2) * BK + 16);
      }
    }
    const int buf = c & 1;
#pragma unroll
    for (int k = 0; k < BK; k++) {
      ulonglong2 b01 = *reinterpret_cast<const ulonglong2*>(&Bs[buf][k][tc * 4]);
      ulonglong2 b23 = *reinterpret_cast<const ulonglong2*>(&Bs[buf][k][128 + tc * 4]);
      float4 a0 = *reinterpret_cast<const float4*>(&As[buf][k][tr * 8]);
      float4 a1 = *reinterpret_cast<const float4*>(&As[buf][k][tr * 8 + 4]);
      ull ap[8];
      ap[0] = pack2(a0.x); ap[1] = pack2(a0.y); ap[2] = pack2(a0.z); ap[3] = pack2(a0.w);
      ap[4] = pack2(a1.x); ap[5] = pack2(a1.y); ap[6] = pack2(a1.z); ap[7] = pack2(a1.w);
#pragma unroll
      for (int r = 0; r < 8; r++) {
        fma2(acc[r][0], ap[r], b01.x);
        fma2(acc[r][1], ap[r], b01.y);
        fma2(acc[r][2], ap[r], b23.x);
        fma2(acc[r][3], ap[r], b23.y);
      }
    }
  }

  // ---- epilogue ----
  const int c0 = tc * 4;
#pragma unroll
  for (int r = 0; r < 8; r++) {
    const int iRow = rowBase + tr * 8 + r;
    if (MODE != 0 && iRow >= cnt) continue;
    const int rr = (MODE == 0) ? iRow : sPerm[tr * 8 + r];
    float f[8];
    {
      float2 v;
      v = unpack2(acc[r][0]); f[0] = v.x; f[1] = v.y;
      v = unpack2(acc[r][1]); f[2] = v.x; f[3] = v.y;
      v = unpack2(acc[r][2]); f[4] = v.x; f[5] = v.y;
      v = unpack2(acc[r][3]); f[6] = v.x; f[7] = v.y;
    }
    const size_t base0 = (size_t)rr * HID + c0;
    const size_t base1 = base0 + 128;
    if (MODE == 0) {
      float4 b0 = *reinterpret_cast<const float4*>(&bias[c0]);
      float4 b1 = *reinterpret_cast<const float4*>(&bias[128 + c0]);
      *reinterpret_cast<float4*>(&g_h[base0]) =
          make_float4(f[0] + b0.x, f[1] + b0.y, f[2] + b0.z, f[3] + b0.w);
      *reinterpret_cast<float4*>(&g_h[base1]) =
          make_float4(f[4] + b1.x, f[5] + b1.y, f[6] + b1.z, f[7] + b1.w);
    } else {
      const int s = g_state[rr] & 7;
      const float* Em = g_E[MODE - 1][s];
      float4 e0 = *reinterpret_cast<const float4*>(&Em[c0]);
      float4 e1 = *reinterpret_cast<const float4*>(&Em[128 + c0]);
      float pre[8] = {f[0] + e0.x, f[1] + e0.y, f[2] + e0.z, f[3] + e0.w,
                      f[4] + e1.x, f[5] + e1.y, f[6] + e1.z, f[7] + e1.w};
      if (MODE == 1) {
        *reinterpret_cast<float4*>(&g_z[base0]) =
            make_float4(sigmoid_(pre[0]), sigmoid_(pre[1]),
                        sigmoid_(pre[2]), sigmoid_(pre[3]));
        *reinterpret_cast<float4*>(&g_z[base1]) =
            make_float4(sigmoid_(pre[4]), sigmoid_(pre[5]),
                        sigmoid_(pre[6]), sigmoid_(pre[7]));
      } else if (MODE == 2) {
        float4 h0 = *reinterpret_cast<const float4*>(&g_h[base0]);
        float4 h1 = *reinterpret_cast<const float4*>(&g_h[base1]);
        *reinterpret_cast<float4*>(&g_rh[base0]) =
            make_float4(sigmoid_(pre[0]) * h0.x, sigmoid_(pre[1]) * h0.y,
                        sigmoid_(pre[2]) * h0.z, sigmoid_(pre[3]) * h0.w);
        *reinterpret_cast<float4*>(&g_rh[base1]) =
            make_float4(sigmoid_(pre[4]) * h1.x, sigmoid_(pre[5]) * h1.y,
                        sigmoid_(pre[6]) * h1.z, sigmoid_(pre[7]) * h1.w);
      } else {
        float4 z0 = *reinterpret_cast<const float4*>(&g_z[base0]);
        float4 z1 = *reinterpret_cast<const float4*>(&g_z[base1]);
        float4 h0 = *reinterpret_cast<const float4*>(&g_h[base0]);
        float4 h1 = *reinterpret_cast<const float4*>(&g_h[base1]);
        float4 o0, o1;
        o0.x = (1.f - z0.x) * h0.x + z0.x * xla_tanh(pre[0]);
        o0.y = (1.f - z0.y) * h0.y + z0.y * xla_tanh(pre[1]);
        o0.z = (1.f - z0.z) * h0.z + z0.z * xla_tanh(pre[2]);
        o0.w = (1.f - z0.w) * h0.w + z0.w * xla_tanh(pre[3]);
        o1.x = (1.f - z1.x) * h1.x + z1.x * xla_tanh(pre[4]);
        o1.y = (1.f - z1.y) * h1.y + z1.y * xla_tanh(pre[5]);
        o1.z = (1.f - z1.z) * h1.z + z1.z * xla_tanh(pre[6]);
        o1.w = (1.f - z1.w) * h1.w + z1.w * xla_tanh(pre[7]);
        *reinterpret_cast<float4*>(&g_h[base0]) = o0;
        *reinterpret_cast<float4*>(&g_h[base1]) = o1;
      }
    }
  }
}

// ---------------- sampler v2 + compaction (R8, unchanged) ---------------------
__global__ void __launch_bounds__(256) sample_step(
    const float* __restrict__ W_out, const float* __restrict__ b_out,
    float* __restrict__ out, int t) {
  __shared__ float Ws[HID * VTOT];
  __shared__ float bs[8];
  __shared__ int wcnt[8], wpre[8], sbase;
  const int cnt = g_cnt[t];
  const int base_i = blockIdx.x * 64;
  if (base_i >= cnt) return;
  const int* perm = g_perm[t & 1];
  int* permN = g_perm[(t + 1) & 1];
  const int tid = threadIdx.x;
  for (int i = tid; i < HID * VTOT; i += 256) Ws[i] = W_out[i];
  if (tid < VTOT) bs[tid] = b_out[tid];
  __syncthreads();
  const int wid = tid >> 5, lane = tid & 31;
  const int g = lane & 3, rloc = lane >> 2;
  const int i = base_i + wid * 8 + rloc;
  const bool valid = (i < cnt);
  const int row = perm[valid ? i : base_i];
  const float* h = g_h + (size_t)row * HID + g * 64;
  float p[VTOT];
#pragma unroll
  for (int v = 0; v < VTOT; v++) p[v] = 0.f;
#pragma unroll
  for (int q = 0; q < 16; q++) {
    float4 hv = *reinterpret_cast<const float4*>(h + q * 4);
    const float* w = &Ws[(g * 64 + q * 4) * VTOT];
#pragma unroll
    for (int v = 0; v < VTOT; v++) {
      p[v] = fmaf(hv.x, w[v], p[v]);
      p[v] = fmaf(hv.y, w[VTOT + v], p[v]);
      p[v] = fmaf(hv.z, w[2 * VTOT + v], p[v]);
      p[v] = fmaf(hv.w, w[3 * VTOT + v], p[v]);
    }
  }
#pragma unroll
  for (int o = 1; o <= 2; o <<= 1)
#pragma unroll
    for (int v = 0; v < VTOT; v++) p[v] += __shfl_xor_sync(0xffffffffu, p[v], o);
  const uint32_t k0 = g_keyw[2 * t], k1 = g_keyw[2 * t + 1];
  float y_best = __int_as_float(0xff800000);
  int tok_best = 127;
  if (g < 3) {
#pragma unroll
    for (int j = 0; j < 2; j++) {
      const int v = 2 * g + j;
      uint32_t idx = (uint32_t)row * VTOT + v;
      uint32_t o0, o1;
      threefry2x32(k0, k1, 0u, idx, o0, o1);
      uint32_t bits = o0 ^ o1;
      uint32_t fb = (bits >> 9) | 0x3f800000u;
      float fu = __fadd_rn(__uint_as_float(fb), -1.0f);
      float u = fmaxf(1.17549435e-38f, fu);
      float gf = -__nv_logf(-__nv_logf(u));
      float y = (p[v] + bs[v]) + gf;
      if (y > y_best) { y_best = y; tok_best = v; }
    }
  }
#pragma unroll
  for (int o = 1; o <= 2; o <<= 1) {
    float y2 = __shfl_xor_sync(0xffffffffu, y_best, o);
    int t2 = __shfl_xor_sync(0xffffffffu, tok_best, o);
    if (y2 > y_best || (y2 == y_best && t2 < tok_best)) { y_best = y2; tok_best = t2; }
  }
  bool active_next = false;
  if (g == 0 && valid) {
    const int tok = tok_best;
    float logits[VTOT];
#pragma unroll
    for (int v = 0; v < VTOT; v++) logits[v] = p[v] + bs[v];
    float mx = logits[0];
#pragma unroll
    for (int v = 1; v < VTOT; v++) mx = fmaxf(mx, logits[v]);
    float ssum = 0.f;
#pragma unroll
    for (int v = 0; v < VTOT; v++)
      ssum = __fadd_rn(ssum, __nv_expf(__fadd_rn(logits[v], -mx)));
    float lp = (logits[tok] - mx) - __nv_logf(ssum);
    out[(size_t)row * 36 + t * VTOT + tok] = 1.f;
    out[(size_t)B_TOT * 36 + row] += lp;
    const bool is_stop = (tok == VTOT - 1);
    if (!is_stop) out[(size_t)B_TOT * 37 + row] += 1.f;
    g_state[row] = (unsigned char)(tok | (is_stop ? 8 : 0));
    active_next = !is_stop;
  }
  unsigned ballot = __ballot_sync(0xffffffffu, active_next);
  int warp_total = __popc(ballot);
  int rank = __popc(ballot & ((1u << lane) - 1u));
  if (lane == 0) wcnt[wid] = warp_total;
  __syncthreads();
  if (tid == 0) {
    int ssum = 0;
#pragma unroll
    for (int w = 0; w < 8; w++) { wpre[w] = ssum; ssum += wcnt[w]; }
    sbase = (ssum > 0) ? atomicAdd(&g_cnt[t + 1], ssum) : 0;
  }
  __syncthreads();
  if (active_next) permN[sbase + wpre[wid] + rank] = row;
}

// ---------------- launch -------------------------------------------------------
extern "C" void kernel_launch(void* const* d_in, const int* in_sizes, int n_in,
                              void* d_out, int out_size) {
  const float* x           = (const float*)d_in[0];
  const float* W_enc       = (const float*)d_in[1];
  const float* b_enc       = (const float*)d_in[2];
  const float* W_embed     = (const float*)d_in[3];
  const float* b_embed     = (const float*)d_in[4];
  const float* W_z         = (const float*)d_in[5];
  const float* b_z         = (const float*)d_in[6];
  const float* W_r         = (const float*)d_in[7];
  const float* b_r         = (const float*)d_in[8];
  const float* W_h         = (const float*)d_in[9];
  const float* b_h         = (const float*)d_in[10];
  const float* W_out       = (const float*)d_in[11];
  const float* b_out       = (const float*)d_in[12];
  const float* start_embed = (const float*)d_in[13];
  float* out = (float*)d_out;

  cudaFuncSetAttribute(gemm_k<0>, cudaFuncAttributeMaxDynamicSharedMemorySize, GSM_TOTAL);
  cudaFuncSetAttribute(gemm_k<1>, cudaFuncAttributeMaxDynamicSharedMemorySize, GSM_TOTAL);
  cudaFuncSetAttribute(gemm_k<2>, cudaFuncAttributeMaxDynamicSharedMemorySize, GSM_TOTAL);
  cudaFuncSetAttribute(gemm_k<3>, cudaFuncAttributeMaxDynamicSharedMemorySize, GSM_TOTAL);

  init_kernel<<<B_TOT / 256, 256>>>(out);
  dim3 gE(8, 3);
  precompute_E<<<gE, 256>>>(W_embed, b_embed, W_z, b_z, W_r, b_r, W_h, b_h,
                            start_embed);

  const int GEMM_GRID = B_TOT / 64;
  gemm_k<0><<<GEMM_GRID, 256, GSM_TOTAL>>>(x, D_IN, D_IN, W_enc, b_enc, 0);

  const float* Wz_bot = W_z + HID * HID;
  const float* Wr_bot = W_r + HID * HID;
  const float* Wh_bot = W_h + HID * HID;

  for (int t = 0; t < TSTEPS; t++) {
    gemm_k<1><<<GEMM_GRID, 256, GSM_TOTAL>>>(nullptr, HID, HID, Wz_bot, nullptr, t);
    gemm_k<2><<<GEMM_GRID, 256, GSM_TOTAL>>>(nullptr, HID, HID, Wr_bot, nullptr, t);
    gemm_k<3><<<GEMM_GRID, 256, GSM_TOTAL>>>(nullptr, HID, HID, Wh_bot, nullptr, t);
    sample_step<<<B_TOT / 64, 256>>>(W_out, b_out, out, t);
  }
}